// round 2
// baseline (speedup 1.0000x reference)
#include <cuda_runtime.h>
#include <mma.h>
#include <cstdint>
#include <math.h>

using namespace nvcuda;

#define Bsz   64
#define Hh    2048
#define G4    8192
#define INs   1024
#define Tt    128
#define STAGES 4
#define BK    32
#define LDA   36
#define LDG   68
#define NLSTM 128
#define NREC  16
#define SMEM_BYTES (STAGES*64*LDA*4*2)

// ---- persistent device scratch (no runtime allocation allowed) ----
__device__ float g_Wih[2L*G4*Hh];          // tf32-rounded W_ih, both layers (128MB)
__device__ float g_Whh[2L*G4*Hh];          // tf32-rounded W_hh (128MB)
__device__ float g_Wrec[(long)INs*Hh];     // tf32-rounded W_rec (8MB)
__device__ float g_h[4L*Bsz*Hh];           // [layer*2+parity][B*H] ping-pong h state
__device__ float g_c[2L*Bsz*Hh];           // [layer][B*H] c state
__device__ float g_x0[(long)Bsz*Hh];       // zero input for t=0

__device__ __forceinline__ float tf32r(float x){
  uint32_t r; asm("cvt.rna.tf32.f32 %0, %1;" : "=r"(r) : "f"(x));
  return __uint_as_float(r);
}
__device__ __forceinline__ uint32_t saddr(const void* p){
  return (uint32_t)__cvta_generic_to_shared(p);
}
__device__ __forceinline__ void cpa16(uint32_t d, const void* s){
  asm volatile("cp.async.cg.shared.global [%0], [%1], 16;" :: "r"(d), "l"(s));
}
__device__ __forceinline__ float sigf(float x){ return 1.f/(1.f+expf(-x)); }

// ---- init: round weights to tf32 (rna), reset state from inputs ----
__global__ void init_kernel(const float* __restrict__ h0, const float* __restrict__ c0,
                            const float* __restrict__ Wih, const float* __restrict__ Whh,
                            const float* __restrict__ Wrec)
{
  long tid = (long)blockIdx.x*blockDim.x + threadIdx.x;
  long stride = (long)gridDim.x*blockDim.x;

  const long NW = (2L*G4*Hh)/4;
  const float4* s1 = (const float4*)Wih; float4* d1 = (float4*)g_Wih;
  const float4* s2 = (const float4*)Whh; float4* d2 = (float4*)g_Whh;
  for (long i=tid;i<NW;i+=stride){
    float4 v=s1[i]; v.x=tf32r(v.x); v.y=tf32r(v.y); v.z=tf32r(v.z); v.w=tf32r(v.w); d1[i]=v;
    float4 u=s2[i]; u.x=tf32r(u.x); u.y=tf32r(u.y); u.z=tf32r(u.z); u.w=tf32r(u.w); d2[i]=u;
  }
  const long NR = ((long)INs*Hh)/4;
  const float4* s3 = (const float4*)Wrec; float4* d3 = (float4*)g_Wrec;
  for (long i=tid;i<NR;i+=stride){
    float4 v=s3[i]; v.x=tf32r(v.x); v.y=tf32r(v.y); v.z=tf32r(v.z); v.w=tf32r(v.w); d3[i]=v;
  }
  const long NS = ((long)Bsz*Hh)/4;   // 32768 float4
  const float4* hs = (const float4*)h0; const float4* cs = (const float4*)c0;
  float4* gh = (float4*)g_h; float4* gc = (float4*)g_c; float4* gx = (float4*)g_x0;
  for (long i=tid;i<NS;i+=stride){
    float4 v0=hs[i];    v0.x=tf32r(v0.x); v0.y=tf32r(v0.y); v0.z=tf32r(v0.z); v0.w=tf32r(v0.w);
    float4 v1=hs[NS+i]; v1.x=tf32r(v1.x); v1.y=tf32r(v1.y); v1.z=tf32r(v1.z); v1.w=tf32r(v1.w);
    gh[1*NS + i] = v0;   // layer0, parity1 (read by step 0)
    gh[3*NS + i] = v1;   // layer1, parity1
    gc[i]      = cs[i];
    gc[NS + i] = cs[NS + i];
    gx[i] = make_float4(0.f,0.f,0.f,0.f);
  }
}

// ---- fused layer-step kernel: GEMM (tf32 wmma) + LSTM cell (or recons) ----
// LSTM CTAs (blockIdx < n_lstm): hidden tile j0..j0+16, all 4 gates (64 gate cols),
//   K = 4096 (concat x | h). Recons CTAs: 64 output cols, K = 2048.
__global__ void __launch_bounds__(256,1) lstm_kernel(
  const float* __restrict__ Ax, const float* __restrict__ Ah,
  const float* __restrict__ Wih, const float* __restrict__ Whh,
  const float* __restrict__ bih, const float* __restrict__ bhh,
  float* __restrict__ c_io, float* __restrict__ h_out,
  int n_lstm,
  const float* __restrict__ Arec, const float* __restrict__ Wrec,
  const float* __restrict__ brec, float* __restrict__ out_rec)
{
  extern __shared__ float smem[];
  float (*As)[64][LDA] = (float(*)[64][LDA])smem;
  float (*Bs)[64][LDA] = (float(*)[64][LDA])(smem + STAGES*64*LDA);

  const int tid = threadIdx.x;
  const bool is_rec = (int)blockIdx.x >= n_lstm;
  const int KT  = is_rec ? (Hh/BK) : (2*Hh/BK);
  const int j0  = is_rec ? 0 : (int)blockIdx.x*16;
  const int rn0 = is_rec ? ((int)blockIdx.x - n_lstm)*64 : 0;
  const float* A0 = is_rec ? Arec : Ax;

  const int sRow = tid >> 3;         // 0..31
  const int sCol = (tid & 7) << 2;   // 0,4,..,28

  auto load_stage = [&](int s, int kt){
    const int kb = kt*BK + sCol;
    #pragma unroll
    for (int h2=0; h2<2; ++h2){
      int r = sRow + h2*32;
      const float* src = (is_rec || kb < Hh) ? (A0 + (long)r*Hh + kb)
                                             : (Ah + (long)r*Hh + (kb - Hh));
      cpa16(saddr(&As[s][r][sCol]), src);
    }
    #pragma unroll
    for (int h2=0; h2<2; ++h2){
      int nn = sRow + h2*32;
      const float* src;
      if (is_rec){
        src = Wrec + (long)(rn0+nn)*Hh + kb;
      } else {
        long row = (long)(nn>>4)*Hh + j0 + (nn&15);   // gate*2048 + j
        src = (kb < Hh) ? (Wih + row*Hh + kb) : (Whh + row*Hh + (kb - Hh));
      }
      cpa16(saddr(&Bs[s][nn][sCol]), src);
    }
    asm volatile("cp.async.commit_group;");
  };

  #pragma unroll
  for (int s=0; s<STAGES-1; ++s) load_stage(s, s);

  using FA = wmma::fragment<wmma::matrix_a,16,16,8,wmma::precision::tf32,wmma::row_major>;
  using FB = wmma::fragment<wmma::matrix_b,16,16,8,wmma::precision::tf32,wmma::col_major>;
  using FC = wmma::fragment<wmma::accumulator,16,16,8,float>;

  const int w   = tid>>5;
  const int grp = w>>2;            // K-split group: 0 -> even k-tiles, 1 -> odd
  const int wi  = w&3;
  const int wm  = (wi>>1)*32;      // warp 32x32 output tile
  const int wn  = (wi&1)*32;

  FC acc[2][2];
  #pragma unroll
  for (int a=0;a<2;a++)
    #pragma unroll
    for (int b=0;b<2;b++) wmma::fill_fragment(acc[a][b], 0.0f);

  for (int kt=0; kt<KT; ++kt){
    asm volatile("cp.async.wait_group 2;");
    __syncthreads();
    const int nx = kt + (STAGES-1);
    if (nx < KT) load_stage(nx & (STAGES-1), nx);
    if ((kt & 1) == grp){
      const int s = kt & (STAGES-1);
      #pragma unroll
      for (int kk=0; kk<BK/8; ++kk){
        FA a[2]; FB b[2];
        #pragma unroll
        for (int mi=0;mi<2;mi++) wmma::load_matrix_sync(a[mi], &As[s][wm+mi*16][kk*8], LDA);
        #pragma unroll
        for (int ni=0;ni<2;ni++) wmma::load_matrix_sync(b[ni], &Bs[s][wn+ni*16][kk*8], LDA);
        #pragma unroll
        for (int mi=0;mi<2;mi++)
          #pragma unroll
          for (int ni=0;ni<2;ni++)
            wmma::mma_sync(acc[mi][ni], a[mi], b[ni], acc[mi][ni]);
      }
    }
  }
  asm volatile("cp.async.wait_group 0;");
  __syncthreads();

  // stage partial sums (two K-split planes) to smem, then combine in epilogue
  float* gp = smem + grp*(64*LDG);
  #pragma unroll
  for (int mi=0;mi<2;mi++)
    #pragma unroll
    for (int ni=0;ni<2;ni++)
      wmma::store_matrix_sync(&gp[(wm+mi*16)*LDG + wn + ni*16], acc[mi][ni], LDG, wmma::mem_row_major);
  __syncthreads();

  const float* p0 = smem;
  const float* p1 = smem + 64*LDG;
  if (!is_rec){
    for (int idx=tid; idx<Bsz*16; idx+=256){
      int b = idx>>4, jj = idx&15, j = j0+jj;
      float iv = p0[b*LDG + jj]      + p1[b*LDG + jj]      + bih[j]        + bhh[j];
      float fv = p0[b*LDG + 16+jj]   + p1[b*LDG + 16+jj]   + bih[Hh+j]    + bhh[Hh+j];
      float gv = p0[b*LDG + 32+jj]   + p1[b*LDG + 32+jj]   + bih[2*Hh+j]  + bhh[2*Hh+j];
      float ov = p0[b*LDG + 48+jj]   + p1[b*LDG + 48+jj]   + bih[3*Hh+j]  + bhh[3*Hh+j];
      float co = c_io[(long)b*Hh + j];
      float cn = sigf(fv)*co + sigf(iv)*tanhf(gv);
      float hn = sigf(ov)*tanhf(cn);
      c_io[(long)b*Hh + j]  = cn;
      h_out[(long)b*Hh + j] = tf32r(hn);   // rounded: next GEMM input
    }
  } else {
    for (int idx=tid; idx<Bsz*64; idx+=256){
      int b = idx>>6, nn = idx&63;
      out_rec[(long)b*INs + rn0 + nn] = p0[b*LDG+nn] + p1[b*LDG+nn] + brec[rn0+nn];
    }
  }
}

extern "C" void kernel_launch(void* const* d_in, const int* in_sizes, int n_in,
                              void* d_out, int out_size)
{
  const float* h0  = (const float*)d_in[1];
  const float* c0  = (const float*)d_in[2];
  const float* Wih = (const float*)d_in[3];
  const float* Whh = (const float*)d_in[4];
  const float* bih = (const float*)d_in[5];
  const float* bhh = (const float*)d_in[6];
  const float* Wrec= (const float*)d_in[7];
  const float* brec= (const float*)d_in[8];
  float* out = (float*)d_out;

  void *p0,*p1,*p2,*p3,*p4,*p5;
  cudaGetSymbolAddress(&p0, g_Wih);
  cudaGetSymbolAddress(&p1, g_Whh);
  cudaGetSymbolAddress(&p2, g_Wrec);
  cudaGetSymbolAddress(&p3, g_h);
  cudaGetSymbolAddress(&p4, g_c);
  cudaGetSymbolAddress(&p5, g_x0);
  float* gWih = (float*)p0; float* gWhh = (float*)p1; float* gWrec = (float*)p2;
  float* gH   = (float*)p3; float* gC   = (float*)p4; float* gX0  = (float*)p5;

  cudaFuncSetAttribute(lstm_kernel, cudaFuncAttributeMaxDynamicSharedMemorySize, SMEM_BYTES);

  init_kernel<<<1024,256>>>(h0, c0, Wih, Whh, Wrec);

  const long NS = (long)Bsz*Hh;         // 131072
  const long WOFF = (long)G4*Hh;        // per-layer weight offset

  for (int t=0; t<Tt; ++t){
    int rp = (t+1)&1, wp = t&1;
    float* h0r = gH + (0*2+rp)*NS;
    float* h0w = gH + (0*2+wp)*NS;
    float* h1r = gH + (1*2+rp)*NS;
    float* h1w = gH + (1*2+wp)*NS;
    const float* x = (t==0) ? gX0 : h1r;
    float* orow = (t==0) ? out : (out + (long)(Tt-t)*Bsz*INs);  // recons of h1(t-1) -> row 128-t

    // layer 0 (+ fused recons of previous step's h1 when t>0)
    lstm_kernel<<<(t==0?NLSTM:NLSTM+NREC),256,SMEM_BYTES>>>(
      x, h0r, gWih, gWhh, bih, bhh, gC, h0w,
      NLSTM, x, gWrec, brec, orow);

    // layer 1
    lstm_kernel<<<NLSTM,256,SMEM_BYTES>>>(
      h0w, h1r, gWih + WOFF, gWhh + WOFF,
      bih + G4, bhh + G4, gC + NS, h1w,
      NLSTM, nullptr, gWrec, brec, nullptr);
  }

  // final recons of h1(127) (parity 1) -> output row 0
  lstm_kernel<<<NREC,256,SMEM_BYTES>>>(
    gX0, gX0, gWih, gWhh, bih, bhh, gC, gX0,
    0, gH + (1*2+1)*NS, gWrec, brec, out);
}

// round 6
// speedup vs baseline: 1.0114x; 1.0114x over previous
#include <cuda_runtime.h>
#include <mma.h>
#include <cstdint>
#include <math.h>

using namespace nvcuda;

#define Bsz   64
#define Hh    2048
#define G4    8192
#define INs   1024
#define Tt    128
#define STAGES 4
#define BK    64
#define LDA   68               // 64 floats + 4 pad
#define LDG   36               // epilogue: 32 cols + 4 pad
#define NLSTM 256
#define NREC  32

#define A_STAGE_FLOATS (64*LDA)            // 4352
#define B_STAGE_FLOATS (32*LDA)            // 2176
#define STAGE_FLOATS   (A_STAGE_FLOATS + B_STAGE_FLOATS)   // 6528 -> 26112 B
#define BSUM_OFF       (STAGES*STAGE_FLOATS)               // 26112 floats
#define SMEM_BYTES     ((BSUM_OFF + 32)*4)                 // 104576 B

// ---- persistent device scratch ----
__device__ float g_Wih[2L*G4*Hh];
__device__ float g_Whh[2L*G4*Hh];
__device__ float g_Wrec[(long)INs*Hh];
__device__ float g_h[4L*Bsz*Hh];
__device__ float g_c[2L*Bsz*Hh];
__device__ float g_x0[(long)Bsz*Hh];

__device__ __forceinline__ float tf32r(float x){
  uint32_t r; asm("cvt.rna.tf32.f32 %0, %1;" : "=r"(r) : "f"(x));
  return __uint_as_float(r);
}
__device__ __forceinline__ uint32_t saddr(const void* p){
  return (uint32_t)__cvta_generic_to_shared(p);
}
__device__ __forceinline__ void cpa16(uint32_t d, const void* s){
  asm volatile("cp.async.cg.shared.global [%0], [%1], 16;" :: "r"(d), "l"(s));
}
__device__ __forceinline__ float sigf(float x){ return 1.f/(1.f+expf(-x)); }

// ---- init: round weights/state to tf32 (rna) ----
__global__ void init_kernel(const float* __restrict__ h0, const float* __restrict__ c0,
                            const float* __restrict__ Wih, const float* __restrict__ Whh,
                            const float* __restrict__ Wrec)
{
  long tid = (long)blockIdx.x*blockDim.x + threadIdx.x;
  long stride = (long)gridDim.x*blockDim.x;

  const long NW = (2L*G4*Hh)/4;
  const float4* s1 = (const float4*)Wih; float4* d1 = (float4*)g_Wih;
  const float4* s2 = (const float4*)Whh; float4* d2 = (float4*)g_Whh;
  for (long i=tid;i<NW;i+=stride){
    float4 v=s1[i]; v.x=tf32r(v.x); v.y=tf32r(v.y); v.z=tf32r(v.z); v.w=tf32r(v.w); d1[i]=v;
    float4 u=s2[i]; u.x=tf32r(u.x); u.y=tf32r(u.y); u.z=tf32r(u.z); u.w=tf32r(u.w); d2[i]=u;
  }
  const long NR = ((long)INs*Hh)/4;
  const float4* s3 = (const float4*)Wrec; float4* d3 = (float4*)g_Wrec;
  for (long i=tid;i<NR;i+=stride){
    float4 v=s3[i]; v.x=tf32r(v.x); v.y=tf32r(v.y); v.z=tf32r(v.z); v.w=tf32r(v.w); d3[i]=v;
  }
  const long NS = ((long)Bsz*Hh)/4;
  const float4* hs = (const float4*)h0; const float4* cs = (const float4*)c0;
  float4* gh = (float4*)g_h; float4* gc = (float4*)g_c; float4* gx = (float4*)g_x0;
  for (long i=tid;i<NS;i+=stride){
    float4 v0=hs[i];    v0.x=tf32r(v0.x); v0.y=tf32r(v0.y); v0.z=tf32r(v0.z); v0.w=tf32r(v0.w);
    float4 v1=hs[NS+i]; v1.x=tf32r(v1.x); v1.y=tf32r(v1.y); v1.z=tf32r(v1.z); v1.w=tf32r(v1.w);
    gh[1*NS + i] = v0;
    gh[3*NS + i] = v1;
    gc[i]      = cs[i];
    gc[NS + i] = cs[NS + i];
    gx[i] = make_float4(0.f,0.f,0.f,0.f);
  }
}

// ---- fused layer-step kernel: wmma tf32 GEMM (64x32xK) + LSTM cell / recons ----
// LSTM CTA: 8 hidden units x 4 gates = 32 gate cols, K = 4096 (concat x|h).
// Recons CTA: 32 output cols, K = 2048.
__global__ void __launch_bounds__(256,2) lstm_kernel(
  const float* __restrict__ Ax, const float* __restrict__ Ah,
  const float* __restrict__ Wih, const float* __restrict__ Whh,
  const float* __restrict__ bih, const float* __restrict__ bhh,
  float* __restrict__ c_io, float* __restrict__ h_out,
  int n_lstm,
  const float* __restrict__ Arec, const float* __restrict__ Wrec,
  const float* __restrict__ brec, float* __restrict__ out_rec)
{
  extern __shared__ float smem[];
  const int tid = threadIdx.x;
  const bool is_rec = (int)blockIdx.x >= n_lstm;
  const int KT  = is_rec ? (Hh/BK) : (2*Hh/BK);        // 32 or 64
  const int j0  = is_rec ? 0 : (int)blockIdx.x*8;
  const int rn0 = is_rec ? ((int)blockIdx.x - n_lstm)*32 : 0;
  const float* A0 = is_rec ? Arec : Ax;

  // bias sums
  if (tid < 32){
    float bs;
    if (is_rec) bs = brec[rn0 + tid];
    else { int g = tid>>3, j = j0 + (tid&7); bs = bih[g*Hh + j] + bhh[g*Hh + j]; }
    smem[BSUM_OFF + tid] = bs;
  }

  // per-thread load mapping
  // A: 1024 x 16B; row = tid>>4 (+16/i), c4 = (tid&15)*4
  // B: 512 x 16B;  row = tid>>4 (+16/i), c4 = (tid&15)*4
  const int aC = (tid & 15) << 2;
  const int aR0 = tid >> 4;
  const float* bw_lo[2]; const float* bw_hi[2];
  #pragma unroll
  for (int i=0;i<2;i++){
    int nn = aR0 + i*16;                    // B row 0..31
    if (is_rec){ bw_lo[i] = Wrec + (long)(rn0+nn)*Hh; bw_hi[i] = bw_lo[i]; }
    else { long wr = (long)(nn>>3)*Hh + j0 + (nn&7); bw_lo[i] = Wih + wr*Hh; bw_hi[i] = Whh + wr*Hh; }
  }

  auto load_stage = [&](int s, int kt){
    const int kb = kt*BK + aC;
    float* stg = smem + s*STAGE_FLOATS;
    const bool lo = (is_rec || kb < Hh);
    #pragma unroll
    for (int i=0;i<4;i++){
      int r = aR0 + i*16;
      const float* src = lo ? (A0 + (long)r*Hh + kb) : (Ah + (long)r*Hh + kb - Hh);
      cpa16(saddr(&stg[r*LDA + aC]), src);
    }
    float* stgB = stg + A_STAGE_FLOATS;
    #pragma unroll
    for (int i=0;i<2;i++){
      int r = aR0 + i*16;
      const float* src = lo ? (bw_lo[i] + kb) : (bw_hi[i] + kb - Hh);
      cpa16(saddr(&stgB[r*LDA + aC]), src);
    }
    asm volatile("cp.async.commit_group;");
  };

  #pragma unroll
  for (int s=0; s<STAGES-1; ++s) load_stage(s, s);

  using FA = wmma::fragment<wmma::matrix_a,16,16,8,wmma::precision::tf32,wmma::row_major>;
  using FB = wmma::fragment<wmma::matrix_b,16,16,8,wmma::precision::tf32,wmma::col_major>;
  using FC = wmma::fragment<wmma::accumulator,16,16,8,float>;

  const int w  = tid>>5;
  const int wm = (w>>1)*16;        // 0,16,32,48
  const int wn = (w&1)*16;         // 0,16

  FC acc;
  wmma::fill_fragment(acc, 0.0f);

  for (int kt=0; kt<KT; ++kt){
    asm volatile("cp.async.wait_group 2;");
    __syncthreads();
    const int nx = kt + (STAGES-1);
    if (nx < KT) load_stage(nx & (STAGES-1), nx);
    const float* stg = smem + (kt & (STAGES-1))*STAGE_FLOATS;
    const float* stgB = stg + A_STAGE_FLOATS;
    #pragma unroll
    for (int kk=0; kk<BK/8; ++kk){
      FA a; FB b;
      wmma::load_matrix_sync(a, &stg[wm*LDA + kk*8], LDA);
      wmma::load_matrix_sync(b, &stgB[wn*LDA + kk*8], LDA);
      wmma::mma_sync(acc, a, b, acc);
    }
  }
  asm volatile("cp.async.wait_group 0;");
  __syncthreads();

  // accum -> smem (reuse stage 0 region), then fused cell / recons epilogue
  wmma::store_matrix_sync(&smem[wm*LDG + wn], acc, LDG, wmma::mem_row_major);
  __syncthreads();

  const float* ep = smem;
  const float* bs = smem + BSUM_OFF;
  if (!is_rec){
    #pragma unroll
    for (int idx=tid; idx<Bsz*8; idx+=256){
      int b = idx>>3, jj = idx&7, j = j0+jj;
      float iv = ep[b*LDG + jj]      + bs[jj];
      float fv = ep[b*LDG + 8+jj]    + bs[8+jj];
      float gv = ep[b*LDG + 16+jj]   + bs[16+jj];
      float ov = ep[b*LDG + 24+jj]   + bs[24+jj];
      float co = c_io[(long)b*Hh + j];
      float cn = sigf(fv)*co + sigf(iv)*tanhf(gv);
      float hn = sigf(ov)*tanhf(cn);
      c_io[(long)b*Hh + j]  = cn;
      h_out[(long)b*Hh + j] = tf32r(hn);
    }
  } else {
    #pragma unroll
    for (int idx=tid; idx<Bsz*32; idx+=256){
      int b = idx>>5, nn = idx&31;
      out_rec[(long)b*INs + rn0 + nn] = ep[b*LDG+nn] + bs[nn];
    }
  }
}

extern "C" void kernel_launch(void* const* d_in, const int* in_sizes, int n_in,
                              void* d_out, int out_size)
{
  const float* h0  = (const float*)d_in[1];
  const float* c0  = (const float*)d_in[2];
  const float* Wih = (const float*)d_in[3];
  const float* Whh = (const float*)d_in[4];
  const float* bih = (const float*)d_in[5];
  const float* bhh = (const float*)d_in[6];
  const float* Wrec= (const float*)d_in[7];
  const float* brec= (const float*)d_in[8];
  float* out = (float*)d_out;

  void *p0,*p1,*p2,*p3,*p4,*p5;
  cudaGetSymbolAddress(&p0, g_Wih);
  cudaGetSymbolAddress(&p1, g_Whh);
  cudaGetSymbolAddress(&p2, g_Wrec);
  cudaGetSymbolAddress(&p3, g_h);
  cudaGetSymbolAddress(&p4, g_c);
  cudaGetSymbolAddress(&p5, g_x0);
  float* gWih = (float*)p0; float* gWhh = (float*)p1; float* gWrec = (float*)p2;
  float* gH   = (float*)p3; float* gC   = (float*)p4; float* gX0  = (float*)p5;

  cudaFuncSetAttribute(lstm_kernel, cudaFuncAttributeMaxDynamicSharedMemorySize, SMEM_BYTES);

  init_kernel<<<1024,256>>>(h0, c0, Wih, Whh, Wrec);

  const long NS = (long)Bsz*Hh;
  const long WOFF = (long)G4*Hh;

  for (int t=0; t<Tt; ++t){
    int rp = (t+1)&1, wp = t&1;
    float* h0r = gH + (0*2+rp)*NS;
    float* h0w = gH + (0*2+wp)*NS;
    float* h1r = gH + (1*2+rp)*NS;
    float* h1w = gH + (1*2+wp)*NS;
    const float* x = (t==0) ? gX0 : h1r;
    float* orow = (t==0) ? out : (out + (long)(Tt-t)*Bsz*INs);

    // layer 0 (+ fused recons of previous step's h1 when t>0)
    lstm_kernel<<<(t==0?NLSTM:NLSTM+NREC),256,SMEM_BYTES>>>(
      x, h0r, gWih, gWhh, bih, bhh, gC, h0w,
      NLSTM, x, gWrec, brec, orow);

    // layer 1
    lstm_kernel<<<NLSTM,256,SMEM_BYTES>>>(
      h0w, h1r, gWih + WOFF, gWhh + WOFF,
      bih + G4, bhh + G4, gC + NS, h1w,
      NLSTM, nullptr, gWrec, brec, nullptr);
  }

  // final recons of h1(127) -> output row 0
  lstm_kernel<<<NREC,256,SMEM_BYTES>>>(
    gX0, gX0, gWih, gWhh, bih, bhh, gC, gX0,
    0, gH + (1*2+1)*NS, gWrec, brec, out);
}